// round 10
// baseline (speedup 1.0000x reference)
#include <cuda_runtime.h>
#include <cuda_bf16.h>
#include <cstdint>
#include <cstddef>

typedef __nv_bfloat16 bf16;
#define NTOK 2048
#define HEADS 8
#define STAGES 3

// ---------------- scratch (static device globals) ----------------
__device__ float g_qkv_cls[(size_t)NTOK * 3072];
__device__ float g_qk_reg [(size_t)NTOK * 2048];
__device__ bf16  g_Xc[(size_t)NTOK * 2048];
__device__ bf16  g_Xr[(size_t)NTOK * 2048];
__device__ bf16  g_Wc[(size_t)3072 * 2048];
__device__ bf16  g_Wr[(size_t)2048 * 2048];
__device__ bf16  g_qc[(size_t)HEADS * NTOK * 256];
__device__ bf16  g_kc[(size_t)HEADS * NTOK * 256];
__device__ bf16  g_qr[(size_t)HEADS * NTOK * 256];
__device__ bf16  g_kr[(size_t)HEADS * NTOK * 256];
__device__ bf16  g_vn[(size_t)NTOK * 2048];             // [n][h*128+d], lo at +1024
__device__ bf16  g_Vt[(size_t)HEADS * 128 * 4096];
__device__ float g_Scls[(size_t)HEADS * NTOK * NTOK];   // scores; later reused for PV partials
__device__ float g_Sreg[(size_t)HEADS * NTOK * NTOK];
__device__ float g_Svv [(size_t)NTOK * NTOK];           // SUM over heads of vn.vn^T (symmetric)
__device__ bf16  g_P[(size_t)HEADS * NTOK * 4096];

// ---------------- helpers ----------------
__device__ __forceinline__ uint32_t s2u(const void* p) {
    uint32_t a;
    asm("{ .reg .u64 t; cvta.to.shared.u64 t, %1; cvt.u32.u64 %0, t; }" : "=r"(a) : "l"(p));
    return a;
}
#define SWZ(x) ((x) ^ (((x) >> 3) & 0x70))

__device__ __forceinline__ void cpasync16(uint32_t s, const void* g) {
    asm volatile("cp.async.cg.shared.global [%0], [%1], 16;" :: "r"(s), "l"(g) : "memory");
}
#define CP_COMMIT() asm volatile("cp.async.commit_group;" ::: "memory")
#define CP_WAIT(n)  asm volatile("cp.async.wait_group %0;" :: "n"(n) : "memory")

__device__ __forceinline__ void ldsm4(uint32_t& r0, uint32_t& r1, uint32_t& r2, uint32_t& r3, uint32_t a) {
    asm volatile("ldmatrix.sync.aligned.m8n8.x4.shared.b16 {%0,%1,%2,%3}, [%4];"
                 : "=r"(r0), "=r"(r1), "=r"(r2), "=r"(r3) : "r"(a));
}
__device__ __forceinline__ void mma16816(float* d, const uint32_t* a, uint32_t b0, uint32_t b1) {
    asm volatile(
        "mma.sync.aligned.m16n8k16.row.col.f32.bf16.bf16.f32 "
        "{%0,%1,%2,%3}, {%4,%5,%6,%7}, {%8,%9}, {%0,%1,%2,%3};"
        : "+f"(d[0]), "+f"(d[1]), "+f"(d[2]), "+f"(d[3])
        : "r"(a[0]), "r"(a[1]), "r"(a[2]), "r"(a[3]), "r"(b0), "r"(b1));
}

// ---------------- HMMA NT GEMM, 64x128 tile, 3 CTAs/SM, parameterless, flat grids ------
// MODE 1: PV split-K  grid (768):  x -> (z = x>>5: head*3+seg, y-tile = x&31)
// MODE 2: qkv merged  grid (1280): x<768 cls 64x128 tile, else reg tile
// MODE 3: scores+vv   grid (8464): x<272 vv symm half-tile (LONG jobs first),
//                                  else score tile: plane z=(x-272)>>9, r=(x-272)&511
template<int MODE>
__global__ __launch_bounds__(256, 3) void hm_gemm_k()
{
    extern __shared__ char dsm[];
    constexpr int NT = 2;                          // n-tiles (of 8) per warp
    constexpr uint32_t ABYTES = 64u * 128u;        // 8KB A tile (64 rows)
    constexpr uint32_t STGB = ABYTES + 16384u;     // + 16KB B tile (128 rows)
    const size_t QH = (size_t)NTOK * 256, SH = (size_t)NTOK * NTOK;

    const bf16 *A, *B; float* C;
    int lda, ldb, ldc, K, i0, j0;
    bool symm = false;
    bool singleseg = false;

    if (MODE == 2) {
        K = 1024; lda = 2048; ldb = 2048;
        const int t = blockIdx.x;
        if (t < 768) {
            A = g_Xc; B = g_Wc; C = g_qkv_cls; ldc = 3072;
            i0 = (t / 24) * 64;  j0 = (t % 24) * 128;
        } else {
            const int t2 = t - 768;
            A = g_Xr; B = g_Wr; C = g_qk_reg; ldc = 2048;
            i0 = (t2 >> 4) * 64;  j0 = (t2 & 15) * 128;
        }
    } else if (MODE == 3) {
        const int x = blockIdx.x;
        if (x < 272) {                 // vv long half-tiles first (LPT scheduling)
            const int p = x >> 1, sub = x & 1;
            int bi = (int)((33.0f - sqrtf(fmaxf(0.0f, 1089.0f - 8.0f * (float)p))) * 0.5f);
            while ((bi + 1) * (33 - (bi + 1)) / 2 <= p) bi++;
            while (bi * (33 - bi) / 2 > p) bi--;
            const int bj = bi + (p - bi * (33 - bi) / 2);
            symm = (bi != bj);
            i0 = bi * 128 + sub * 64; j0 = bj * 128;
            A = g_vn; B = g_vn; C = g_Svv; lda = 2048; ldb = 2048; ldc = 2048; K = 1024;
        } else {
            const int t = x - 272;
            const int z = t >> 9, r = t & 511;
            K = 128; lda = 256; ldb = 256; ldc = 2048;
            if (z < 8) { A = g_qc + z * QH;       B = g_kc + z * QH;       C = g_Scls + z * SH; }
            else       { A = g_qr + (z - 8) * QH; B = g_kr + (z - 8) * QH; C = g_Sreg + (z - 8) * SH; }
            i0 = (r >> 4) * 64;  j0 = (r & 15) * 128;
        }
    } else {  // MODE 1: PV
        singleseg = true;
        const int z = blockIdx.x >> 5, yt = blockIdx.x & 31;
        const int head = z / 3, seg = z % 3;
        K = 2048;
        A = g_P  + (size_t)head * NTOK * 4096 + ((seg == 1) ? (size_t)K : 0);
        B = g_Vt + (size_t)head * 128  * 4096 + ((seg == 2) ? (size_t)K : 0);
        C = g_Scls + (size_t)z * NTOK * 128;
        lda = 4096; ldb = 4096; ldc = 128;
        i0 = yt * 64; j0 = 0;
    }

    const int nkc = K >> 6;
    const int NC  = singleseg ? nkc : 3 * nkc;
    const int tid = threadIdx.x;
    const uint32_t stage0 = (s2u(dsm) + 1023u) & ~1023u;

    const int lane = tid & 31, wid = tid >> 5;
    const int wn = wid;                            // 8 n-warps, single m-warp
    const int lt = lane >> 3, lr = lane & 7;
    const int arow = (lt & 1) * 8 + lr;            // + mt*16
    const int brow = wn * 16 + (lt & 1) * 8 + lr;  // + np*16 (np=0 only)
    const int kbsub = (lt >> 1) * 16;
    const uint32_t xm = (uint32_t)(lr << 4);

    float acc[4][NT][4];
#pragma unroll
    for (int i = 0; i < 4; i++)
#pragma unroll
        for (int j = 0; j < NT; j++)
#pragma unroll
            for (int q = 0; q < 4; q++) acc[i][j][q] = 0.0f;

    auto fill = [&](int s, int c) {
        const bf16 *Ab, *Bb;
        if (MODE == 1) {
            const int kk = c << 6;
            Ab = A + kk;  Bb = B + kk;
        } else {
            const int seg = c / nkc, kk = (c - seg * nkc) << 6;
            Ab = A + ((seg == 1) ? K : 0) + kk;
            Bb = B + ((seg == 2) ? K : 0) + kk;
        }
        const uint32_t sA = stage0 + (uint32_t)s * STGB, sB = sA + ABYTES;
#pragma unroll
        for (int i = 0; i < 2; i++) {              // 64 rows x 8 groups / 256 thr
            const int id = (i << 8) + tid;
            const int row = id >> 3, c16 = id & 7;
            const uint32_t so = SWZ((uint32_t)((row << 7) + (c16 << 4)));
            cpasync16(sA + so, Ab + (size_t)(i0 + row) * lda + (c16 << 3));
        }
#pragma unroll
        for (int i = 0; i < 4; i++) {              // 128 rows x 8 groups / 256 thr
            const int id = (i << 8) + tid;
            const int row = id >> 3, c16 = id & 7;
            const uint32_t so = SWZ((uint32_t)((row << 7) + (c16 << 4)));
            cpasync16(sB + so, Bb + (size_t)(j0 + row) * ldb + (c16 << 3));
        }
    };

#pragma unroll
    for (int c = 0; c < STAGES; c++) { fill(c, c); CP_COMMIT(); }

    for (int c = 0; c < NC; ++c) {
        const int s = c - (c / STAGES) * STAGES;
        CP_WAIT(1);
        __syncthreads();
        if (c >= 1) {
            const int cn = c + 2;
            if (cn < NC) fill(cn - (cn / STAGES) * STAGES, cn);
            CP_COMMIT();
        }
        const uint32_t sA = stage0 + (uint32_t)s * STGB, sB = sA + ABYTES;
#pragma unroll
        for (int ks = 0; ks < 4; ks++) {
            const uint32_t koff = ((uint32_t)(ks * 32 + kbsub)) ^ xm;
            uint32_t a[4][4], b[4];
#pragma unroll
            for (int mt = 0; mt < 4; mt++)
                ldsm4(a[mt][0], a[mt][1], a[mt][2], a[mt][3],
                      sA + (uint32_t)((arow + mt * 16) << 7) + koff);
            ldsm4(b[0], b[1], b[2], b[3],
                  sB + (uint32_t)(brow << 7) + koff);
#pragma unroll
            for (int mt = 0; mt < 4; mt++)
#pragma unroll
                for (int nt = 0; nt < NT; nt++)
                    mma16816(acc[mt][nt], a[mt], b[nt & 1], b[(nt & 1) + 2]);
        }
    }

    const int rq = lane >> 2, cq = (lane & 3) * 2;
#pragma unroll
    for (int mt = 0; mt < 4; mt++) {
        const int row = i0 + mt * 16 + rq;
#pragma unroll
        for (int nt = 0; nt < NT; nt++) {
            const int col = j0 + wn * 16 + nt * 8 + cq;
            *(float2*)(C + (size_t)row * ldc + col)       = make_float2(acc[mt][nt][0], acc[mt][nt][1]);
            *(float2*)(C + (size_t)(row + 8) * ldc + col) = make_float2(acc[mt][nt][2], acc[mt][nt][3]);
        }
    }

    // mirror off-diagonal vv 64x128 tile -> 128x64 via padded smem transpose
    if (MODE == 3) {
        if (symm) {
            float* smf = (float*)dsm;              // 64 x 133 fp32 = 34KB < DS
            __syncthreads();
#pragma unroll
            for (int mt = 0; mt < 4; mt++) {
                const int r = mt * 16 + rq;        // 0..63
#pragma unroll
                for (int nt = 0; nt < NT; nt++) {
                    const int cc = wn * 16 + nt * 8 + cq;   // 0..127
                    smf[r * 133 + cc]           = acc[mt][nt][0];
                    smf[r * 133 + cc + 1]       = acc[mt][nt][1];
                    smf[(r + 8) * 133 + cc]     = acc[mt][nt][2];
                    smf[(r + 8) * 133 + cc + 1] = acc[mt][nt][3];
                }
            }
            __syncthreads();
            const int a2 = tid >> 1;               // mirror row 0..127 (orig col)
            const int bbase = (tid & 1) * 32;      // mirror col half (orig row)
            float* Crow = C + (size_t)(j0 + a2) * ldc + i0 + bbase;
#pragma unroll
            for (int q = 0; q < 8; q++) {
                const int b = bbase + q * 4;
                float4 v = make_float4(smf[(b + 0) * 133 + a2],
                                       smf[(b + 1) * 133 + a2],
                                       smf[(b + 2) * 133 + a2],
                                       smf[(b + 3) * 133 + a2]);
                *(float4*)(Crow + q * 4 - bbase + 0) = v;   // Crow already offset by bbase
            }
        }
    }
}

// ---------------- PV split-K reduce + x_ori copy fused ----------------
__global__ __launch_bounds__(256) void pv_finish(const float* __restrict__ part, float* __restrict__ out)
{
    const size_t t = (size_t)blockIdx.x * 256 + threadIdx.x;   // over 2048*2048/4
    const size_t e = t * 4;
    const int n = (int)(e >> 11), c = (int)(e & 2047);
    if (c < 1024) {
        const int h = c >> 7, d = c & 127;
        const size_t base = (((size_t)h * 3 * NTOK) + n) * 128 + d;
        const size_t sg = (size_t)NTOK * 128;
        float4 v0 = *(const float4*)(part + base);
        float4 v1 = *(const float4*)(part + base + sg);
        float4 v2 = *(const float4*)(part + base + 2 * sg);
        *(float4*)(out + (size_t)n * 2048 + c) =
            make_float4(v0.x + v1.x + v2.x, v0.y + v1.y + v2.y,
                        v0.z + v1.z + v2.z, v0.w + v1.w + v2.w);
    } else {
        *(float4*)(out + (size_t)n * 2048 + c) =
            *(const float4*)(g_qkv_cls + (size_t)n * 3072 + 1024 + c);
    }
}

// ---------------- fp32 -> bf16 hi|lo split ----------------
__global__ __launch_bounds__(256) void split_x(const float* __restrict__ xc, const float* __restrict__ xr)
{
    const size_t i = (size_t)blockIdx.x * 256 + threadIdx.x;
    const int n = (int)(i >> 10), c = (int)(i & 1023);
    const float v = (blockIdx.z == 0 ? xc : xr)[i];
    bf16* o = (blockIdx.z == 0 ? g_Xc : g_Xr) + (size_t)n * 2048 + c;
    const bf16 h = __float2bfloat16(v);
    o[0] = h;  o[1024] = __float2bfloat16(v - __bfloat162float(h));
}

// ---------------- transpose + split: fp32 [R][C] -> bf16 [C][ldout], lo at +R ---------
__global__ __launch_bounds__(256) void transpose_split(
    const float* __restrict__ in, bf16* __restrict__ out,
    int R, int C, int ldin, int ldout, size_t zin, size_t zout)
{
    __shared__ float t[32][33];
    in  += (size_t)blockIdx.z * zin;
    out += (size_t)blockIdx.z * zout;
    const int r0 = blockIdx.y * 32, c0 = blockIdx.x * 32;
    const int tx = threadIdx.x & 31, ty = threadIdx.x >> 5;
#pragma unroll
    for (int i = 0; i < 4; i++)
        t[ty + i * 8][tx] = in[(size_t)(r0 + ty + i * 8) * ldin + c0 + tx];
    __syncthreads();
#pragma unroll
    for (int i = 0; i < 4; i++) {
        const int cc = ty + i * 8;
        const float v = t[tx][cc];
        const bf16 h = __float2bfloat16(v);
        out[(size_t)(c0 + cc) * ldout + r0 + tx]     = h;
        out[(size_t)(c0 + cc) * ldout + R + r0 + tx] = __float2bfloat16(v - __bfloat162float(h));
    }
}

// ---------------- L2-normalize + split ----------------
__global__ __launch_bounds__(256) void normalize_k()
{
    const int gid  = blockIdx.x * 8 + (threadIdx.x >> 5);
    const int lane = threadIdx.x & 31;
    const int op  = gid / (NTOK * HEADS);
    const int rem = gid - op * (NTOK * HEADS);
    const int n = rem >> 3, h = rem & 7;

    const float* src; bf16* dst; int lo_off;
    if (op == 0)      { src = g_qkv_cls + (size_t)n * 3072 + h * 128;        dst = g_qc + ((size_t)h * NTOK + n) * 256; lo_off = 128; }
    else if (op == 1) { src = g_qkv_cls + (size_t)n * 3072 + 1024 + h * 128; dst = g_kc + ((size_t)h * NTOK + n) * 256; lo_off = 128; }
    else if (op == 2) { src = g_qk_reg  + (size_t)n * 2048 + h * 128;        dst = g_qr + ((size_t)h * NTOK + n) * 256; lo_off = 128; }
    else if (op == 3) { src = g_qk_reg  + (size_t)n * 2048 + 1024 + h * 128; dst = g_kr + ((size_t)h * NTOK + n) * 256; lo_off = 128; }
    else              { src = g_qkv_cls + (size_t)n * 3072 + 2048 + h * 128; dst = g_vn + (size_t)n * 2048 + h * 128;   lo_off = 1024; }

    float4 v = *(const float4*)(src + lane * 4);
    float ss = v.x * v.x + v.y * v.y + v.z * v.z + v.w * v.w;
#pragma unroll
    for (int o = 16; o; o >>= 1) ss += __shfl_xor_sync(0xffffffffu, ss, o);
    const float r = 1.0f / sqrtf(ss);
    float a[4] = { v.x * r, v.y * r, v.z * r, v.w * r };
#pragma unroll
    for (int j = 0; j < 4; j++) {
        const bf16 h2 = __float2bfloat16(a[j]);
        dst[lane * 4 + j]          = h2;
        dst[lo_off + lane * 4 + j] = __float2bfloat16(a[j] - __bfloat162float(h2));
    }
}

// ---------------- FMA-only exp + block reductions ----------------
__device__ __forceinline__ float fast_exp(float x)
{
    float t = x * 1.4426950408889634f;
    t = fmaxf(t, -120.0f);
    float r = t + 12582912.0f;
    float f = t - (r - 12582912.0f);
    int   k = __float_as_int(r) - 0x4B400000;
    float p = 1.5403530393381609e-4f;
    p = fmaf(p, f, 1.3333558146428443e-3f);
    p = fmaf(p, f, 9.618129107628477e-3f);
    p = fmaf(p, f, 5.550410866482158e-2f);
    p = fmaf(p, f, 2.402265069591007e-1f);
    p = fmaf(p, f, 6.931471805599453e-1f);
    p = fmaf(p, f, 1.0f);
    return p * __int_as_float((k + 127) << 23);
}
__device__ __forceinline__ float block_max(float v, float* red)
{
#pragma unroll
    for (int o = 16; o; o >>= 1) v = fmaxf(v, __shfl_xor_sync(0xffffffffu, v, o));
    if ((threadIdx.x & 31) == 0) red[threadIdx.x >> 5] = v;
    __syncthreads();
    float r = red[0];
#pragma unroll
    for (int i = 1; i < 8; i++) r = fmaxf(r, red[i]);
    __syncthreads();
    return r;
}
__device__ __forceinline__ float block_sum(float v, float* red)
{
#pragma unroll
    for (int o = 16; o; o >>= 1) v += __shfl_xor_sync(0xffffffffu, v, o);
    if ((threadIdx.x & 31) == 0) red[threadIdx.x >> 5] = v;
    __syncthreads();
    float r = red[0];
#pragma unroll
    for (int i = 1; i < 8; i++) r += red[i];
    __syncthreads();
    return r;
}

// ---------------- fused masked dual softmax + combine + sim_round2 -----------------
__global__ __launch_bounds__(256) void row_fuse(
    const float* __restrict__ cls_score, const float* __restrict__ fg_score,
    float* __restrict__ out_sim)
{
    const int n = blockIdx.x;
    const int tid = threadIdx.x;
    const int m0 = tid * 8;
    __shared__ float s_sc[NTOK];
    __shared__ float red[8];

    float fc[8], fr[8];
    float lsc = -1e30f, lfs = -1e30f;
#pragma unroll
    for (int j = 0; j < 8; j++) {
        const int m = m0 + j;
        const float a = cls_score[m], b = fg_score[m];
        fc[j] = a;  fr[j] = b;
        s_sc[m] = a;
        lsc = fmaxf(lsc, a);  lfs = fmaxf(lfs, b);
    }
    __syncthreads();
    const float Mc = 25.0f * block_max(lsc, red) + 1.0f;
    const float Mr = 25.0f * block_max(lfs, red) + 1.0f;
    const float cthr = s_sc[n] - 0.1f;
    const float fthr = fg_score[n] - 0.1f;
#pragma unroll
    for (int j = 0; j < 8; j++) {
        fc[j] = (fc[j] > cthr) ? 25.0f * fc[j] : 0.0f;
        fr[j] = (fr[j] > fthr) ? 25.0f * fr[j] : 0.0f;
    }

    float vvacc[8];
    {
        float4 v0 = *(const float4*)(g_Svv + (size_t)n * NTOK + m0);
        float4 v1 = *(const float4*)(g_Svv + (size_t)n * NTOK + m0 + 4);
        vvacc[0] = v0.x; vvacc[1] = v0.y; vvacc[2] = v0.z; vvacc[3] = v0.w;
        vvacc[4] = v1.x; vvacc[5] = v1.y; vvacc[6] = v1.z; vvacc[7] = v1.w;
    }

    float simacc[8];
#pragma unroll
    for (int j = 0; j < 8; j++) simacc[j] = 0.0f;

    for (int h = 0; h < HEADS; h++) {
        const size_t base = ((size_t)h * NTOK + n) * NTOK + m0;
        bf16* Pb = g_P + ((size_t)h * NTOK + n) * 4096 + m0;
        float ec[8], er[8];

        float4 s0 = *(const float4*)(g_Scls + base);
        float4 s1 = *(const float4*)(g_Scls + base + 4);
        ec[0] = fast_exp(s0.x * fc[0] - Mc);  ec[1] = fast_exp(s0.y * fc[1] - Mc);
        ec[2] = fast_exp(s0.z * fc[2] - Mc);  ec[3] = fast_exp(s0.w * fc[3] - Mc);
        ec[4] = fast_exp(s1.x * fc[4] - Mc);  ec[5] = fast_exp(s1.y * fc[5] - Mc);
        ec[6] = fast_exp(s1.z * fc[6] - Mc);  ec[7] = fast_exp(s1.w * fc[7] - Mc);
        float smc = ec[0] + ec[1] + ec[2] + ec[3] + ec[4] + ec[5] + ec[6] + ec[7];

        float4 r0 = *(const float4*)(g_Sreg + base);
        float4 r1 = *(const float4*)(g_Sreg + base + 4);
        er[0] = fast_exp(r0.x * fr[0] - Mr);  er[1] = fast_exp(r0.y * fr[1] - Mr);
        er[2] = fast_exp(r0.z * fr[2] - Mr);  er[3] = fast_exp(r0.w * fr[3] - Mr);
        er[4] = fast_exp(r1.x * fr[4] - Mr);  er[5] = fast_exp(r1.y * fr[5] - Mr);
        er[6] = fast_exp(r1.z * fr[6] - Mr);  er[7] = fast_exp(r1.w * fr[7] - Mr);
        float smr = er[0] + er[1] + er[2] + er[3] + er[4] + er[5] + er[6] + er[7];

        smc = block_sum(smc, red);
        smr = block_sum(smr, red);
        const float ic = 0.5f / smc, ir = 0.5f / smr;

        float pv[8];
#pragma unroll
        for (int j = 0; j < 8; j++) pv[j] = ec[j] * ic + er[j] * ir;

        union { __nv_bfloat162 h2[4]; uint4 u; } ph, pl;
#pragma unroll
        for (int j = 0; j < 4; j++) {
            const bf16 h0 = __float2bfloat16(pv[2 * j]);
            const bf16 h1 = __float2bfloat16(pv[2 * j + 1]);
            ph.h2[j] = __nv_bfloat162(h0, h1);
            pl.h2[j] = __nv_bfloat162(
                __float2bfloat16(pv[2 * j]     - __bfloat162float(h0)),
                __float2bfloat16(pv[2 * j + 1] - __bfloat162float(h1)));
        }
        *(uint4*)(Pb)        = ph.u;
        *(uint4*)(Pb + 2048) = pl.u;

#pragma unroll
        for (int j = 0; j < 8; j++) simacc[j] += pv[j];
    }

    float sm = 0.0f;
#pragma unroll
    for (int j = 0; j < 8; j++) { simacc[j] = fast_exp(simacc[j] * 0.125f - 1.0f); sm += simacc[j]; }
    sm = block_sum(sm, red);
    float msum = 0.0f;
#pragma unroll
    for (int j = 0; j < 8; j++) {
        const float soft = simacc[j] / sm;
        const float keep = (vvacc[j] > 6.0f) ? soft : 0.0f;
        simacc[j] = keep; msum += keep;
    }
    msum = block_sum(msum, red);
    const float rn = 1.0f / msum;
    float4 o0 = make_float4(simacc[0] * rn, simacc[1] * rn, simacc[2] * rn, simacc[3] * rn);
    float4 o1 = make_float4(simacc[4] * rn, simacc[5] * rn, simacc[6] * rn, simacc[7] * rn);
    *(float4*)(out_sim + (size_t)n * NTOK + m0)     = o0;
    *(float4*)(out_sim + (size_t)n * NTOK + m0 + 4) = o1;
}

// -------------------------------- launch ----------------------------------------
extern "C" void kernel_launch(void* const* d_in, const int* in_sizes, int n_in,
                              void* d_out, int out_size)
{
    (void)in_sizes; (void)n_in; (void)out_size;
    const float* x_cls     = (const float*)d_in[0];
    const float* x_reg     = (const float*)d_in[1];
    const float* cls_score = (const float*)d_in[2];
    const float* fg_score  = (const float*)d_in[3];
    const float* W_cls     = (const float*)d_in[4];
    const float* W_reg     = (const float*)d_in[5];
    float* out = (float*)d_out;

    float *qkv_cls, *Scls;
    bf16 *Wc, *Wr, *Vt;
    cudaGetSymbolAddress((void**)&qkv_cls, g_qkv_cls);
    cudaGetSymbolAddress((void**)&Wc, g_Wc);
    cudaGetSymbolAddress((void**)&Wr, g_Wr);
    cudaGetSymbolAddress((void**)&Vt, g_Vt);
    cudaGetSymbolAddress((void**)&Scls, g_Scls);

    const int DS = STAGES * 24576 + 1024;   // 64x128 tile stages; 3 CTAs/SM
    cudaFuncSetAttribute((const void*)hm_gemm_k<1>, cudaFuncAttributeMaxDynamicSharedMemorySize, DS);
    cudaFuncSetAttribute((const void*)hm_gemm_k<2>, cudaFuncAttributeMaxDynamicSharedMemorySize, DS);
    cudaFuncSetAttribute((const void*)hm_gemm_k<3>, cudaFuncAttributeMaxDynamicSharedMemorySize, DS);

    // 1) split inputs, transpose+split weights
    split_x<<<dim3(8192, 1, 2), 256>>>(x_cls, x_reg);
    transpose_split<<<dim3(96, 32, 1), 256>>>(W_cls, Wc, 1024, 3072, 3072, 2048, 0, 0);
    transpose_split<<<dim3(64, 32, 1), 256>>>(W_reg, Wr, 1024, 2048, 3072, 2048, 0, 0);

    // 2) qkv projections, cls+reg merged, 64x128 tiles, flat grid
    hm_gemm_k<2><<<1280, 256, DS>>>();

    // 3) normalize q/k/v; transpose v -> Vt split
    normalize_k<<<5 * NTOK * HEADS / 8, 256>>>();
    transpose_split<<<dim3(4, 64, 8), 256>>>(qkv_cls + 2048, Vt, 2048, 128, 3072, 4096,
                                             128, (size_t)128 * 4096);

    // 4) scores (16 planes x 512 tiles) + symmetric vv (272 half-tiles FIRST)
    hm_gemm_k<3><<<8464, 256, DS>>>();

    // 5) fused softmax + sim (reads S*, writes P bf16 hi|lo + sim output)
    row_fuse<<<NTOK, 256>>>(cls_score, fg_score, out + (size_t)NTOK * NTOK);

    // 6) x = P @ V split-K partials (reuse g_Scls), then reduce + x_ori
    hm_gemm_k<1><<<768, 256, DS>>>();
    pv_finish<<<(NTOK * 2048 / 4) / 256, 256>>>(Scls, out);
}

// round 11
// speedup vs baseline: 1.0333x; 1.0333x over previous
#include <cuda_runtime.h>
#include <cuda_bf16.h>
#include <cstdint>
#include <cstddef>

typedef __nv_bfloat16 bf16;
#define NTOK 2048
#define HEADS 8
#define STAGES 3

// ---------------- scratch (static device globals) ----------------
__device__ float g_qkv_cls[(size_t)NTOK * 3072];
__device__ float g_qk_reg [(size_t)NTOK * 2048];
__device__ bf16  g_Xc[(size_t)NTOK * 2048];
__device__ bf16  g_Xr[(size_t)NTOK * 2048];
__device__ bf16  g_Wc[(size_t)3072 * 2048];
__device__ bf16  g_Wr[(size_t)2048 * 2048];
__device__ bf16  g_qc[(size_t)HEADS * NTOK * 256];
__device__ bf16  g_kc[(size_t)HEADS * NTOK * 256];
__device__ bf16  g_qr[(size_t)HEADS * NTOK * 256];
__device__ bf16  g_kr[(size_t)HEADS * NTOK * 256];
__device__ bf16  g_vn[(size_t)NTOK * 2048];             // [n][h*128+d], lo at +1024
__device__ bf16  g_Vt[(size_t)HEADS * 128 * 4096];
__device__ float g_Scls[(size_t)HEADS * NTOK * NTOK];   // scores; later reused for PV partials
__device__ float g_Sreg[(size_t)HEADS * NTOK * NTOK];
__device__ float g_Svv [(size_t)NTOK * NTOK];           // SUM over heads of vn.vn^T (symmetric)
__device__ bf16  g_P[(size_t)HEADS * NTOK * 4096];

// ---------------- helpers ----------------
__device__ __forceinline__ uint32_t s2u(const void* p) {
    uint32_t a;
    asm("{ .reg .u64 t; cvta.to.shared.u64 t, %1; cvt.u32.u64 %0, t; }" : "=r"(a) : "l"(p));
    return a;
}
#define SWZ(x) ((x) ^ (((x) >> 3) & 0x70))

__device__ __forceinline__ void cpasync16(uint32_t s, const void* g) {
    asm volatile("cp.async.cg.shared.global [%0], [%1], 16;" :: "r"(s), "l"(g) : "memory");
}
#define CP_COMMIT() asm volatile("cp.async.commit_group;" ::: "memory")
#define CP_WAIT(n)  asm volatile("cp.async.wait_group %0;" :: "n"(n) : "memory")

__device__ __forceinline__ void ldsm4(uint32_t& r0, uint32_t& r1, uint32_t& r2, uint32_t& r3, uint32_t a) {
    asm volatile("ldmatrix.sync.aligned.m8n8.x4.shared.b16 {%0,%1,%2,%3}, [%4];"
                 : "=r"(r0), "=r"(r1), "=r"(r2), "=r"(r3) : "r"(a));
}
__device__ __forceinline__ void mma16816(float* d, const uint32_t* a, uint32_t b0, uint32_t b1) {
    asm volatile(
        "mma.sync.aligned.m16n8k16.row.col.f32.bf16.bf16.f32 "
        "{%0,%1,%2,%3}, {%4,%5,%6,%7}, {%8,%9}, {%0,%1,%2,%3};"
        : "+f"(d[0]), "+f"(d[1]), "+f"(d[2]), "+f"(d[3])
        : "r"(a[0]), "r"(a[1]), "r"(a[2]), "r"(a[3]), "r"(b0), "r"(b1));
}

// ---------------- HMMA NT GEMM, per-mode tile selection, parameterless, flat grids ----
// MODE 1: PV split-K  MW=1 (64x128, 3 CTA/SM)  grid 768:  z=x>>5 (head*3+seg), yt=x&31
// MODE 2: qkv merged  MW=1 (64x128, 3 CTA/SM)  grid 1280: x<768 cls tile, else reg tile
// MODE 3: scores+vv   MW=2 (128x128, 2 CTA/SM) grid 4232: x<136 vv symm tile FIRST,
//                                              else score tile z=(x-136)>>8, r=(x-136)&255
template<int MODE>
__global__ __launch_bounds__(256, (MODE == 3) ? 2 : 3) void hm_gemm_k()
{
    extern __shared__ char dsm[];
    constexpr int MW = (MODE == 3) ? 2 : 1;
    constexpr int NT = 2 * MW;                     // n-tiles (of 8) per warp
    constexpr int NP = NT / 2;                     // b ldsm.x4 per warp
    constexpr int MROWS = MW * 64;
    constexpr uint32_t ABYTES = (uint32_t)MROWS * 128u;
    constexpr uint32_t STGB = ABYTES + 16384u;
    const size_t QH = (size_t)NTOK * 256, SH = (size_t)NTOK * NTOK;

    const bf16 *A, *B; float* C;
    int lda, ldb, ldc, K, i0, j0;
    bool symm = false; int bi = 0, bj = 0;
    bool singleseg = false;

    if (MODE == 2) {
        K = 1024; lda = 2048; ldb = 2048;
        const int t = blockIdx.x;
        if (t < 768) {
            A = g_Xc; B = g_Wc; C = g_qkv_cls; ldc = 3072;
            i0 = (t / 24) * 64;  j0 = (t % 24) * 128;
        } else {
            const int t2 = t - 768;
            A = g_Xr; B = g_Wr; C = g_qk_reg; ldc = 2048;
            i0 = (t2 >> 4) * 64;  j0 = (t2 & 15) * 128;
        }
    } else if (MODE == 3) {
        const int x = blockIdx.x;
        if (x < 136) {                 // vv long tiles first (LPT scheduling)
            symm = true;
            bi = (int)((33.0f - sqrtf(fmaxf(0.0f, 1089.0f - 8.0f * (float)x))) * 0.5f);
            while ((bi + 1) * (33 - (bi + 1)) / 2 <= x) bi++;
            while (bi * (33 - bi) / 2 > x) bi--;
            bj = bi + (x - bi * (33 - bi) / 2);
            i0 = bi * 128; j0 = bj * 128;
            A = g_vn; B = g_vn; C = g_Svv; lda = 2048; ldb = 2048; ldc = 2048; K = 1024;
        } else {
            const int t = x - 136;
            const int z = t >> 8, r = t & 255;
            K = 128; lda = 256; ldb = 256; ldc = 2048;
            if (z < 8) { A = g_qc + z * QH;       B = g_kc + z * QH;       C = g_Scls + z * SH; }
            else       { A = g_qr + (z - 8) * QH; B = g_kr + (z - 8) * QH; C = g_Sreg + (z - 8) * SH; }
            i0 = (r >> 4) * 128;  j0 = (r & 15) * 128;
        }
    } else {  // MODE 1: PV
        singleseg = true;
        const int z = blockIdx.x >> 5, yt = blockIdx.x & 31;
        const int head = z / 3, seg = z % 3;
        K = 2048;
        A = g_P  + (size_t)head * NTOK * 4096 + ((seg == 1) ? (size_t)K : 0);
        B = g_Vt + (size_t)head * 128  * 4096 + ((seg == 2) ? (size_t)K : 0);
        C = g_Scls + (size_t)z * NTOK * 128;
        lda = 4096; ldb = 4096; ldc = 128;
        i0 = yt * 64; j0 = 0;
    }

    const int nkc = K >> 6;
    const int NC  = singleseg ? nkc : 3 * nkc;
    const int tid = threadIdx.x;
    const uint32_t stage0 = (s2u(dsm) + 1023u) & ~1023u;

    const int lane = tid & 31, wid = tid >> 5;
    const int wm = wid % MW, wn = wid / MW;
    const int lt = lane >> 3, lr = lane & 7;
    const int arow = wm * 64 + (lt & 1) * 8 + lr;
    const int brow = wn * (NT * 8) + (lt & 1) * 8 + lr;
    const int kbsub = (lt >> 1) * 16;
    const uint32_t xm = (uint32_t)(lr << 4);

    float acc[4][NT][4];
#pragma unroll
    for (int i = 0; i < 4; i++)
#pragma unroll
        for (int j = 0; j < NT; j++)
#pragma unroll
            for (int q = 0; q < 4; q++) acc[i][j][q] = 0.0f;

    auto fill = [&](int s, int c) {
        const bf16 *Ab, *Bb;
        if (MODE == 1) {
            const int kk = c << 6;
            Ab = A + kk;  Bb = B + kk;
        } else {
            const int seg = c / nkc, kk = (c - seg * nkc) << 6;
            Ab = A + ((seg == 1) ? K : 0) + kk;
            Bb = B + ((seg == 2) ? K : 0) + kk;
        }
        const uint32_t sA = stage0 + (uint32_t)s * STGB, sB = sA + ABYTES;
#pragma unroll
        for (int i = 0; i < 2 * MW; i++) {
            const int id = (i << 8) + tid;
            const int row = id >> 3, c16 = id & 7;
            const uint32_t so = SWZ((uint32_t)((row << 7) + (c16 << 4)));
            cpasync16(sA + so, Ab + (size_t)(i0 + row) * lda + (c16 << 3));
        }
#pragma unroll
        for (int i = 0; i < 4; i++) {
            const int id = (i << 8) + tid;
            const int row = id >> 3, c16 = id & 7;
            const uint32_t so = SWZ((uint32_t)((row << 7) + (c16 << 4)));
            cpasync16(sB + so, Bb + (size_t)(j0 + row) * ldb + (c16 << 3));
        }
    };

#pragma unroll
    for (int c = 0; c < STAGES; c++) { fill(c, c); CP_COMMIT(); }

    for (int c = 0; c < NC; ++c) {
        const int s = c - (c / STAGES) * STAGES;
        CP_WAIT(1);
        __syncthreads();
        if (c >= 1) {
            const int cn = c + 2;
            if (cn < NC) fill(cn - (cn / STAGES) * STAGES, cn);
            CP_COMMIT();
        }
        const uint32_t sA = stage0 + (uint32_t)s * STGB, sB = sA + ABYTES;
#pragma unroll
        for (int ks = 0; ks < 4; ks++) {
            const uint32_t koff = ((uint32_t)(ks * 32 + kbsub)) ^ xm;
            uint32_t a[4][4], b[NP][4];
#pragma unroll
            for (int mt = 0; mt < 4; mt++)
                ldsm4(a[mt][0], a[mt][1], a[mt][2], a[mt][3],
                      sA + (uint32_t)((arow + mt * 16) << 7) + koff);
#pragma unroll
            for (int np = 0; np < NP; np++)
                ldsm4(b[np][0], b[np][1], b[np][2], b[np][3],
                      sB + (uint32_t)((brow + np * 16) << 7) + koff);
#pragma unroll
            for (int mt = 0; mt < 4; mt++)
#pragma unroll
                for (int nt = 0; nt < NT; nt++)
                    mma16816(acc[mt][nt], a[mt], b[nt >> 1][nt & 1], b[nt >> 1][(nt & 1) + 2]);
        }
    }

    const int rq = lane >> 2, cq = (lane & 3) * 2;
#pragma unroll
    for (int mt = 0; mt < 4; mt++) {
        const int row = i0 + wm * 64 + mt * 16 + rq;
#pragma unroll
        for (int nt = 0; nt < NT; nt++) {
            const int col = j0 + wn * (NT * 8) + nt * 8 + cq;
            *(float2*)(C + (size_t)row * ldc + col)       = make_float2(acc[mt][nt][0], acc[mt][nt][1]);
            *(float2*)(C + (size_t)(row + 8) * ldc + col) = make_float2(acc[mt][nt][2], acc[mt][nt][3]);
        }
    }

    // mirror off-diagonal vv tile via padded smem transpose (MODE 3 only, MW=2)
    if (MODE == 3) {
        if (symm && bi != bj) {
            float* smf = (float*)dsm;              // 128 x 133 fp32 = 68KB < DS2
            __syncthreads();
#pragma unroll
            for (int mt = 0; mt < 4; mt++) {
                const int r = wm * 64 + mt * 16 + rq;
#pragma unroll
                for (int nt = 0; nt < NT; nt++) {
                    const int cc = wn * (NT * 8) + nt * 8 + cq;
                    smf[r * 133 + cc]           = acc[mt][nt][0];
                    smf[r * 133 + cc + 1]       = acc[mt][nt][1];
                    smf[(r + 8) * 133 + cc]     = acc[mt][nt][2];
                    smf[(r + 8) * 133 + cc + 1] = acc[mt][nt][3];
                }
            }
            __syncthreads();
            const int r2 = tid & 127;
            const int c2b = (tid >> 7) * 64;
            float* Crow = C + (size_t)(j0 + r2) * ldc + i0 + c2b;
#pragma unroll
            for (int q = 0; q < 16; q++) {
                float4 v = make_float4(smf[(c2b + 4 * q + 0) * 133 + r2],
                                       smf[(c2b + 4 * q + 1) * 133 + r2],
                                       smf[(c2b + 4 * q + 2) * 133 + r2],
                                       smf[(c2b + 4 * q + 3) * 133 + r2]);
                *(float4*)(Crow + 4 * q) = v;
            }
        }
    }
}

// ---------------- PV split-K reduce + x_ori copy fused ----------------
__global__ __launch_bounds__(256) void pv_finish(const float* __restrict__ part, float* __restrict__ out)
{
    const size_t t = (size_t)blockIdx.x * 256 + threadIdx.x;   // over 2048*2048/4
    const size_t e = t * 4;
    const int n = (int)(e >> 11), c = (int)(e & 2047);
    if (c < 1024) {
        const int h = c >> 7, d = c & 127;
        const size_t base = (((size_t)h * 3 * NTOK) + n) * 128 + d;
        const size_t sg = (size_t)NTOK * 128;
        float4 v0 = *(const float4*)(part + base);
        float4 v1 = *(const float4*)(part + base + sg);
        float4 v2 = *(const float4*)(part + base + 2 * sg);
        *(float4*)(out + (size_t)n * 2048 + c) =
            make_float4(v0.x + v1.x + v2.x, v0.y + v1.y + v2.y,
                        v0.z + v1.z + v2.z, v0.w + v1.w + v2.w);
    } else {
        *(float4*)(out + (size_t)n * 2048 + c) =
            *(const float4*)(g_qkv_cls + (size_t)n * 3072 + 1024 + c);
    }
}

// ---------------- fp32 -> bf16 hi|lo split ----------------
__global__ __launch_bounds__(256) void split_x(const float* __restrict__ xc, const float* __restrict__ xr)
{
    const size_t i = (size_t)blockIdx.x * 256 + threadIdx.x;
    const int n = (int)(i >> 10), c = (int)(i & 1023);
    const float v = (blockIdx.z == 0 ? xc : xr)[i];
    bf16* o = (blockIdx.z == 0 ? g_Xc : g_Xr) + (size_t)n * 2048 + c;
    const bf16 h = __float2bfloat16(v);
    o[0] = h;  o[1024] = __float2bfloat16(v - __bfloat162float(h));
}

// ---------------- transpose + split: fp32 [R][C] -> bf16 [C][ldout], lo at +R ---------
__global__ __launch_bounds__(256) void transpose_split(
    const float* __restrict__ in, bf16* __restrict__ out,
    int R, int C, int ldin, int ldout, size_t zin, size_t zout)
{
    __shared__ float t[32][33];
    in  += (size_t)blockIdx.z * zin;
    out += (size_t)blockIdx.z * zout;
    const int r0 = blockIdx.y * 32, c0 = blockIdx.x * 32;
    const int tx = threadIdx.x & 31, ty = threadIdx.x >> 5;
#pragma unroll
    for (int i = 0; i < 4; i++)
        t[ty + i * 8][tx] = in[(size_t)(r0 + ty + i * 8) * ldin + c0 + tx];
    __syncthreads();
#pragma unroll
    for (int i = 0; i < 4; i++) {
        const int cc = ty + i * 8;
        const float v = t[tx][cc];
        const bf16 h = __float2bfloat16(v);
        out[(size_t)(c0 + cc) * ldout + r0 + tx]     = h;
        out[(size_t)(c0 + cc) * ldout + R + r0 + tx] = __float2bfloat16(v - __bfloat162float(h));
    }
}

// ---------------- L2-normalize + split ----------------
__global__ __launch_bounds__(256) void normalize_k()
{
    const int gid  = blockIdx.x * 8 + (threadIdx.x >> 5);
    const int lane = threadIdx.x & 31;
    const int op  = gid / (NTOK * HEADS);
    const int rem = gid - op * (NTOK * HEADS);
    const int n = rem >> 3, h = rem & 7;

    const float* src; bf16* dst; int lo_off;
    if (op == 0)      { src = g_qkv_cls + (size_t)n * 3072 + h * 128;        dst = g_qc + ((size_t)h * NTOK + n) * 256; lo_off = 128; }
    else if (op == 1) { src = g_qkv_cls + (size_t)n * 3072 + 1024 + h * 128; dst = g_kc + ((size_t)h * NTOK + n) * 256; lo_off = 128; }
    else if (op == 2) { src = g_qk_reg  + (size_t)n * 2048 + h * 128;        dst = g_qr + ((size_t)h * NTOK + n) * 256; lo_off = 128; }
    else if (op == 3) { src = g_qk_reg  + (size_t)n * 2048 + 1024 + h * 128; dst = g_kr + ((size_t)h * NTOK + n) * 256; lo_off = 128; }
    else              { src = g_qkv_cls + (size_t)n * 3072 + 2048 + h * 128; dst = g_vn + (size_t)n * 2048 + h * 128;   lo_off = 1024; }

    float4 v = *(const float4*)(src + lane * 4);
    float ss = v.x * v.x + v.y * v.y + v.z * v.z + v.w * v.w;
#pragma unroll
    for (int o = 16; o; o >>= 1) ss += __shfl_xor_sync(0xffffffffu, ss, o);
    const float r = 1.0f / sqrtf(ss);
    float a[4] = { v.x * r, v.y * r, v.z * r, v.w * r };
#pragma unroll
    for (int j = 0; j < 4; j++) {
        const bf16 h2 = __float2bfloat16(a[j]);
        dst[lane * 4 + j]          = h2;
        dst[lo_off + lane * 4 + j] = __float2bfloat16(a[j] - __bfloat162float(h2));
    }
}

// ---------------- FMA-only exp + block reductions ----------------
__device__ __forceinline__ float fast_exp(float x)
{
    float t = x * 1.4426950408889634f;
    t = fmaxf(t, -120.0f);
    float r = t + 12582912.0f;
    float f = t - (r - 12582912.0f);
    int   k = __float_as_int(r) - 0x4B400000;
    float p = 1.5403530393381609e-4f;
    p = fmaf(p, f, 1.3333558146428443e-3f);
    p = fmaf(p, f, 9.618129107628477e-3f);
    p = fmaf(p, f, 5.550410866482158e-2f);
    p = fmaf(p, f, 2.402265069591007e-1f);
    p = fmaf(p, f, 6.931471805599453e-1f);
    p = fmaf(p, f, 1.0f);
    return p * __int_as_float((k + 127) << 23);
}
__device__ __forceinline__ float block_max(float v, float* red)
{
#pragma unroll
    for (int o = 16; o; o >>= 1) v = fmaxf(v, __shfl_xor_sync(0xffffffffu, v, o));
    if ((threadIdx.x & 31) == 0) red[threadIdx.x >> 5] = v;
    __syncthreads();
    float r = red[0];
#pragma unroll
    for (int i = 1; i < 8; i++) r = fmaxf(r, red[i]);
    __syncthreads();
    return r;
}
__device__ __forceinline__ float block_sum(float v, float* red)
{
#pragma unroll
    for (int o = 16; o; o >>= 1) v += __shfl_xor_sync(0xffffffffu, v, o);
    if ((threadIdx.x & 31) == 0) red[threadIdx.x >> 5] = v;
    __syncthreads();
    float r = red[0];
#pragma unroll
    for (int i = 1; i < 8; i++) r += red[i];
    __syncthreads();
    return r;
}

// ---------------- fused masked dual softmax + combine + sim_round2 -----------------
__global__ __launch_bounds__(256) void row_fuse(
    const float* __restrict__ cls_score, const float* __restrict__ fg_score,
    float* __restrict__ out_sim)
{
    const int n = blockIdx.x;
    const int tid = threadIdx.x;
    const int m0 = tid * 8;
    __shared__ float s_sc[NTOK];
    __shared__ float red[8];

    float fc[8], fr[8];
    float lsc = -1e30f, lfs = -1e30f;
#pragma unroll
    for (int j = 0; j < 8; j++) {
        const int m = m0 + j;
        const float a = cls_score[m], b = fg_score[m];
        fc[j] = a;  fr[j] = b;
        s_sc[m] = a;
        lsc = fmaxf(lsc, a);  lfs = fmaxf(lfs, b);
    }
    __syncthreads();
    const float Mc = 25.0f * block_max(lsc, red) + 1.0f;
    const float Mr = 25.0f * block_max(lfs, red) + 1.0f;
    const float cthr = s_sc[n] - 0.1f;
    const float fthr = fg_score[n] - 0.1f;
#pragma unroll
    for (int j = 0; j < 8; j++) {
        fc[j] = (fc[j] > cthr) ? 25.0f * fc[j] : 0.0f;
        fr[j] = (fr[j] > fthr) ? 25.0f * fr[j] : 0.0f;
    }

    float vvacc[8];
    {
        float4 v0 = *(const float4*)(g_Svv + (size_t)n * NTOK + m0);
        float4 v1 = *(const float4*)(g_Svv + (size_t)n * NTOK + m0 + 4);
        vvacc[0] = v0.x; vvacc[1] = v0.y; vvacc[2] = v0.z; vvacc[3] = v0.w;
        vvacc[4] = v1.x; vvacc[5] = v1.y; vvacc[6] = v1.z; vvacc[7] = v1.w;
    }

    float simacc[8];
#pragma unroll
    for (int j = 0; j < 8; j++) simacc[j] = 0.0f;

    for (int h = 0; h < HEADS; h++) {
        const size_t base = ((size_t)h * NTOK + n) * NTOK + m0;
        bf16* Pb = g_P + ((size_t)h * NTOK + n) * 4096 + m0;
        float ec[8], er[8];

        float4 s0 = *(const float4*)(g_Scls + base);
        float4 s1 = *(const float4*)(g_Scls + base + 4);
        ec[0] = fast_exp(s0.x * fc[0] - Mc);  ec[1] = fast_exp(s0.y * fc[1] - Mc);
        ec[2] = fast_exp(s0.z * fc[2] - Mc);  ec[3] = fast_exp(s0.w * fc[3] - Mc);
        ec[4] = fast_exp(s1.x * fc[4] - Mc);  ec[5] = fast_exp(s1.y * fc[5] - Mc);
        ec[6] = fast_exp(s1.z * fc[6] - Mc);  ec[7] = fast_exp(s1.w * fc[7] - Mc);
        float smc = ec[0] + ec[1] + ec[2] + ec[3] + ec[4] + ec[5] + ec[6] + ec[7];

        float4 r0 = *(const float4*)(g_Sreg + base);
        float4 r1 = *(const float4*)(g_Sreg + base + 4);
        er[0] = fast_exp(r0.x * fr[0] - Mr);  er[1] = fast_exp(r0.y * fr[1] - Mr);
        er[2] = fast_exp(r0.z * fr[2] - Mr);  er[3] = fast_exp(r0.w * fr[3] - Mr);
        er[4] = fast_exp(r1.x * fr[4] - Mr);  er[5] = fast_exp(r1.y * fr[5] - Mr);
        er[6] = fast_exp(r1.z * fr[6] - Mr);  er[7] = fast_exp(r1.w * fr[7] - Mr);
        float smr = er[0] + er[1] + er[2] + er[3] + er[4] + er[5] + er[6] + er[7];

        smc = block_sum(smc, red);
        smr = block_sum(smr, red);
        const float ic = 0.5f / smc, ir = 0.5f / smr;

        float pv[8];
#pragma unroll
        for (int j = 0; j < 8; j++) pv[j] = ec[j] * ic + er[j] * ir;

        union { __nv_bfloat162 h2[4]; uint4 u; } ph, pl;
#pragma unroll
        for (int j = 0; j < 4; j++) {
            const bf16 h0 = __float2bfloat16(pv[2 * j]);
            const bf16 h1 = __float2bfloat16(pv[2 * j + 1]);
            ph.h2[j] = __nv_bfloat162(h0, h1);
            pl.h2[j] = __nv_bfloat162(
                __float2bfloat16(pv[2 * j]     - __bfloat162float(h0)),
                __float2bfloat16(pv[2 * j + 1] - __bfloat162float(h1)));
        }
        *(uint4*)(Pb)        = ph.u;
        *(uint4*)(Pb + 2048) = pl.u;

#pragma unroll
        for (int j = 0; j < 8; j++) simacc[j] += pv[j];
    }

    float sm = 0.0f;
#pragma unroll
    for (int j = 0; j < 8; j++) { simacc[j] = fast_exp(simacc[j] * 0.125f - 1.0f); sm += simacc[j]; }
    sm = block_sum(sm, red);
    float msum = 0.0f;
#pragma unroll
    for (int j = 0; j < 8; j++) {
        const float soft = simacc[j] / sm;
        const float keep = (vvacc[j] > 6.0f) ? soft : 0.0f;
        simacc[j] = keep; msum += keep;
    }
    msum = block_sum(msum, red);
    const float rn = 1.0f / msum;
    float4 o0 = make_float4(simacc[0] * rn, simacc[1] * rn, simacc[2] * rn, simacc[3] * rn);
    float4 o1 = make_float4(simacc[4] * rn, simacc[5] * rn, simacc[6] * rn, simacc[7] * rn);
    *(float4*)(out_sim + (size_t)n * NTOK + m0)     = o0;
    *(float4*)(out_sim + (size_t)n * NTOK + m0 + 4) = o1;
}

// -------------------------------- launch ----------------------------------------
extern "C" void kernel_launch(void* const* d_in, const int* in_sizes, int n_in,
                              void* d_out, int out_size)
{
    (void)in_sizes; (void)n_in; (void)out_size;
    const float* x_cls     = (const float*)d_in[0];
    const float* x_reg     = (const float*)d_in[1];
    const float* cls_score = (const float*)d_in[2];
    const float* fg_score  = (const float*)d_in[3];
    const float* W_cls     = (const float*)d_in[4];
    const float* W_reg     = (const float*)d_in[5];
    float* out = (float*)d_out;

    float *qkv_cls, *Scls;
    bf16 *Wc, *Wr, *Vt;
    cudaGetSymbolAddress((void**)&qkv_cls, g_qkv_cls);
    cudaGetSymbolAddress((void**)&Wc, g_Wc);
    cudaGetSymbolAddress((void**)&Wr, g_Wr);
    cudaGetSymbolAddress((void**)&Vt, g_Vt);
    cudaGetSymbolAddress((void**)&Scls, g_Scls);

    const int DS1 = STAGES * 24576 + 1024;   // MW=1 stages (64x128), 3 CTAs/SM
    const int DS2 = STAGES * 32768 + 1024;   // MW=2 stages (128x128), 2 CTAs/SM
    cudaFuncSetAttribute((const void*)hm_gemm_k<1>, cudaFuncAttributeMaxDynamicSharedMemorySize, DS1);
    cudaFuncSetAttribute((const void*)hm_gemm_k<2>, cudaFuncAttributeMaxDynamicSharedMemorySize, DS1);
    cudaFuncSetAttribute((const void*)hm_gemm_k<3>, cudaFuncAttributeMaxDynamicSharedMemorySize, DS2);

    // 1) split inputs, transpose+split weights
    split_x<<<dim3(8192, 1, 2), 256>>>(x_cls, x_reg);
    transpose_split<<<dim3(96, 32, 1), 256>>>(W_cls, Wc, 1024, 3072, 3072, 2048, 0, 0);
    transpose_split<<<dim3(64, 32, 1), 256>>>(W_reg, Wr, 1024, 2048, 3072, 2048, 0, 0);

    // 2) qkv projections, cls+reg merged, 64x128 tiles @ 3 CTA/SM
    hm_gemm_k<2><<<1280, 256, DS1>>>();

    // 3) normalize q/k/v; transpose v -> Vt split
    normalize_k<<<5 * NTOK * HEADS / 8, 256>>>();
    transpose_split<<<dim3(4, 64, 8), 256>>>(qkv_cls + 2048, Vt, 2048, 128, 3072, 4096,
                                             128, (size_t)128 * 4096);

    // 4) scores (16 planes) + symmetric vv, 128x128 tiles @ 2 CTA/SM, vv LPT-first
    hm_gemm_k<3><<<4232, 256, DS2>>>();

    // 5) fused softmax + sim (reads S*, writes P bf16 hi|lo + sim output)
    row_fuse<<<NTOK, 256>>>(cls_score, fg_score, out + (size_t)NTOK * NTOK);

    // 6) x = P @ V split-K partials (reuse g_Scls), 64x128 @ 3 CTA/SM, then finish
    hm_gemm_k<1><<<768, 256, DS1>>>();
    pv_finish<<<(NTOK * 2048 / 4) / 256, 256>>>(Scls, out);
}